// round 1
// baseline (speedup 1.0000x reference)
#include <cuda_runtime.h>
#include <math.h>

#define FM_C 256
#define FM_H 200
#define FM_W 200
#define IIH 201
#define IIW 201
#define NBOX 1024
#define OH 7
#define OW 7

// Integral image scratch, channel-last layout: [y][x][c], y,x in 0..200.
// g_ii[y][x][c] = sum_{y'<y, x'<x} fm[c][y'][x']
__device__ float g_ii[IIH * IIW * FM_C];  // 41.4 MB

// ---------------------------------------------------------------------------
// K0: zero the padding (y=0 plane and x=0 column)
// ---------------------------------------------------------------------------
__global__ void k0_zero_pad() {
    int idx = blockIdx.x * blockDim.x + threadIdx.x;
    // y = 0 plane: [0][x][c], x in 0..200 -> IIW*FM_C elements
    if (idx < IIW * FM_C) {
        g_ii[idx] = 0.0f;
    }
    // x = 0 column for y = 1..200: (IIH-1)*FM_C elements
    if (idx < (IIH - 1) * FM_C) {
        int y = idx / FM_C + 1;
        int c = idx % FM_C;
        g_ii[(y * IIW) * FM_C + c] = 0.0f;
    }
}

// ---------------------------------------------------------------------------
// K1: cumsum over y, fused with transpose [C][H][W] -> [y+1][x+1][C]
// Block handles a (TC=32 channels) x (TX=16 x-positions) tile, loops y=0..199.
// Depth-4 register prefetch hides DRAM latency across the per-y barriers.
// ---------------------------------------------------------------------------
#define TX 16
#define TC 32
__global__ void __launch_bounds__(512) k1_ycum_transpose(const float* __restrict__ fm) {
    __shared__ float sh[TC * (TX + 1)];
    const int tid = threadIdx.x;           // 0..511
    const int x0 = blockIdx.x * TX;
    const int c0 = blockIdx.y * TC;

    // Load-side mapping: contiguous x within a 16-thread group (coalesced reads)
    const int xx = tid & (TX - 1);         // 0..15
    const int cc = tid >> 4;               // 0..31
    const int xr = x0 + xx;
    const bool valid = (xr < FM_W);
    const float* src = fm + (size_t)(c0 + cc) * (FM_H * FM_W) + xr;

    // Store-side mapping: contiguous c within a warp (coalesced 128B writes)
    const int c_out = tid & 31;            // 0..31
    const int x_out = tid >> 5;            // 0..15
    const bool validw = (x0 + x_out) < FM_W;
    float* dstbase = g_ii + (size_t)(x0 + x_out + 1) * FM_C + (c0 + c_out);

    float acc = 0.0f;
    float v0 = valid ? src[0 * FM_W] : 0.0f;
    float v1 = valid ? src[1 * FM_W] : 0.0f;
    float v2 = valid ? src[2 * FM_W] : 0.0f;
    float v3 = valid ? src[3 * FM_W] : 0.0f;

    #pragma unroll 1
    for (int y = 0; y < FM_H; y++) {
        acc += v0;
        v0 = v1; v1 = v2; v2 = v3;
        const int yn = y + 4;
        v3 = (valid && yn < FM_H) ? src[yn * FM_W] : 0.0f;

        sh[cc * (TX + 1) + xx] = acc;
        __syncthreads();
        if (validw) {
            dstbase[(size_t)(y + 1) * (IIW * FM_C)] = sh[c_out * (TX + 1) + x_out];
        }
        __syncthreads();
    }
}

// ---------------------------------------------------------------------------
// K2: cumsum over x, in-place, channel-last layout. Thread per (y, c).
// All accesses 128B-coalesced per warp; loads independent of the serial acc.
// ---------------------------------------------------------------------------
__global__ void __launch_bounds__(256) k2_xcum() {
    const int y = blockIdx.x + 1;          // 1..200
    const int c = threadIdx.x;             // 0..255
    float* row = g_ii + (size_t)(y * IIW) * FM_C + c;
    float acc = 0.0f;
    #pragma unroll 4
    for (int x = 1; x <= FM_W; x++) {
        float v = row[(size_t)x * FM_C];
        acc += v;
        row[(size_t)x * FM_C] = acc;
    }
}

// ---------------------------------------------------------------------------
// K3: gather. One block per box; thread = channel. 4-corner lookups per bin
// are 128B-coalesced warp reads from L2-resident ii. Results staged through
// shared so the global writes are flat & coalesced.
// ---------------------------------------------------------------------------
__global__ void __launch_bounds__(256) k3_gather(const float* __restrict__ boxes,
                                                 float* __restrict__ out) {
    __shared__ float sh[FM_C * 25];        // 25.6 KB
    const int n = blockIdx.x;
    const int tid = threadIdx.x;
    const int c = tid;

    const float bx1 = boxes[n * 4 + 0];
    const float by1 = boxes[n * 4 + 1];
    const float bx2 = boxes[n * 4 + 2];
    const float by2 = boxes[n * 4 + 3];

    // scale = 200/800 = 0.25 exactly (power of two -> bit-exact with reference)
    const int b0 = (int)floorf(bx1 * 0.25f);
    const int b1 = (int)floorf(by1 * 0.25f);
    const int b2 = (int)floorf(bx2 * 0.25f);
    const int b3 = (int)floorf(by2 * 0.25f);

    const int x1 = min(max(b0, 0), FM_W - 1);
    const int y1 = min(max(b1, 0), FM_H - 1);
    const int x2 = min(max(b2 + 1, x1 + 1), FM_W);
    const int y2 = min(max(b3 + 1, y1 + 1), FM_H);
    const int rh = y2 - y1;
    const int rw = x2 - x1;

    int rs[OH], re[OH], cs[OW], ce[OW];
    #pragma unroll
    for (int i = 0; i < OH; i++) {
        rs[i] = y1 + (i * rh) / OH;
        re[i] = y1 + ((i + 1) * rh + OH - 1) / OH;
        cs[i] = x1 + (i * rw) / OW;
        ce[i] = x1 + ((i + 1) * rw + OW - 1) / OW;
    }

    const float* base = g_ii + c;

    #pragma unroll
    for (int p = 0; p < 2; p++) {
        #pragma unroll
        for (int b = 0; b < 25; b++) {
            const int bin = p * 25 + b;
            if (bin < OH * OW) {
                const int i = bin / OW;
                const int j = bin % OW;
                const float A = base[(size_t)(re[i] * IIW + ce[j]) * FM_C];
                const float B = base[(size_t)(rs[i] * IIW + ce[j]) * FM_C];
                const float C = base[(size_t)(re[i] * IIW + cs[j]) * FM_C];
                const float D = base[(size_t)(rs[i] * IIW + cs[j]) * FM_C];
                const float area = (float)((re[i] - rs[i]) * (ce[j] - cs[j]));
                sh[c * 25 + b] = (A - B - C + D) / area;
            }
        }
        __syncthreads();
        const int nbins = (p == 0) ? 25 : 24;
        for (int idx = tid; idx < FM_C * nbins; idx += 256) {
            const int cc = idx / nbins;
            const int bb = idx % nbins;
            out[(size_t)n * (FM_C * OH * OW) + cc * (OH * OW) + p * 25 + bb] =
                sh[cc * 25 + bb];
        }
        __syncthreads();
    }
}

// ---------------------------------------------------------------------------
extern "C" void kernel_launch(void* const* d_in, const int* in_sizes, int n_in,
                              void* d_out, int out_size) {
    const float* fm    = (const float*)d_in[0];   // [1,256,200,200] fp32
    const float* boxes = (const float*)d_in[1];   // [1024,4] fp32
    float* out = (float*)d_out;                   // [1024,256,7,7] fp32

    // K0: zero pads
    {
        int nmax = IIW * FM_C;  // 51456 (covers both pad regions)
        k0_zero_pad<<<(nmax + 255) / 256, 256>>>();
    }
    // K1: y-cumsum + transpose
    {
        dim3 grid((FM_W + TX - 1) / TX, FM_C / TC);  // (13, 8)
        k1_ycum_transpose<<<grid, 512>>>(fm);
    }
    // K2: x-cumsum
    k2_xcum<<<FM_H, 256>>>();
    // K3: gather
    k3_gather<<<NBOX, 256>>>(boxes, out);
}

// round 2
// speedup vs baseline: 1.1549x; 1.1549x over previous
#include <cuda_runtime.h>
#include <math.h>

#define FM_C 256
#define FM_H 200
#define FM_W 200
#define IIH 201
#define IIW 201
#define NBOX 1024
#define OH 7
#define OW 7
#define NBINS 49

// Integral image scratch, channel-last layout: [y][x][c], y,x in 0..200.
__device__ float g_ii[IIH * IIW * FM_C];  // 41.4 MB

// ---------------------------------------------------------------------------
// K0: zero the padding (y=0 plane and x=0 column)
// ---------------------------------------------------------------------------
__global__ void k0_zero_pad() {
    int idx = blockIdx.x * blockDim.x + threadIdx.x;
    if (idx < IIW * FM_C) {
        g_ii[idx] = 0.0f;
    }
    if (idx < (IIH - 1) * FM_C) {
        int y = idx / FM_C + 1;
        int c = idx % FM_C;
        g_ii[(y * IIW) * FM_C + c] = 0.0f;
    }
}

// ---------------------------------------------------------------------------
// K1: cumsum over y, fused with transpose [C][H][W] -> [y+1][x+1][C]
// Double-buffered shared tile: one barrier per y iteration.
// ---------------------------------------------------------------------------
#define TX 16
#define TC 32
__global__ void __launch_bounds__(512) k1_ycum_transpose(const float* __restrict__ fm) {
    __shared__ float sh[2][TC * (TX + 1)];
    const int tid = threadIdx.x;           // 0..511
    const int x0 = blockIdx.x * TX;
    const int c0 = blockIdx.y * TC;

    // Load-side mapping: contiguous x within a 16-thread group (coalesced reads)
    const int xx = tid & (TX - 1);         // 0..15
    const int cc = tid >> 4;               // 0..31
    const int xr = x0 + xx;
    const bool valid = (xr < FM_W);
    const float* src = fm + (size_t)(c0 + cc) * (FM_H * FM_W) + xr;

    // Store-side mapping: contiguous c within a warp (coalesced 128B writes)
    const int c_out = tid & 31;            // 0..31
    const int x_out = tid >> 5;            // 0..15
    const bool validw = (x0 + x_out) < FM_W;
    float* dstbase = g_ii + (size_t)(x0 + x_out + 1) * FM_C + (c0 + c_out);

    float acc = 0.0f;
    float v0 = valid ? src[0 * FM_W] : 0.0f;
    float v1 = valid ? src[1 * FM_W] : 0.0f;
    float v2 = valid ? src[2 * FM_W] : 0.0f;
    float v3 = valid ? src[3 * FM_W] : 0.0f;

    #pragma unroll 1
    for (int y = 0; y < FM_H; y++) {
        acc += v0;
        v0 = v1; v1 = v2; v2 = v3;
        const int yn = y + 4;
        v3 = (valid && yn < FM_H) ? src[yn * FM_W] : 0.0f;

        const int buf = y & 1;
        sh[buf][cc * (TX + 1) + xx] = acc;
        __syncthreads();
        if (validw) {
            dstbase[(size_t)(y + 1) * (IIW * FM_C)] = sh[buf][c_out * (TX + 1) + x_out];
        }
        // no second barrier: next iter writes the other buffer; by the time this
        // buffer is written again (y+2), all threads passed the y+1 barrier,
        // which is after every read of this buffer.
    }
}

// ---------------------------------------------------------------------------
// K2: cumsum over x, in-place, channel-last layout. Thread per (y, c).
// ---------------------------------------------------------------------------
__global__ void __launch_bounds__(256) k2_xcum() {
    const int y = blockIdx.x + 1;          // 1..200
    const int c = threadIdx.x;             // 0..255
    float* row = g_ii + (size_t)(y * IIW) * FM_C + c;
    float acc = 0.0f;
    #pragma unroll 8
    for (int x = 1; x <= FM_W; x++) {
        float v = row[(size_t)x * FM_C];
        acc += v;
        row[(size_t)x * FM_C] = acc;
    }
}

// ---------------------------------------------------------------------------
// K3: gather. One block per box.
//  setup : 49 threads precompute 4 corner float4-offsets + 1/area per bin
//  phase1: 256 threads = 64 channel-groups (float4) x 4 bin slots; fat 16B
//          gathers from L2-resident ii, stage result in shared [c][bin]
//  phase2: flat coalesced write-out, compile-time bin-count division
// ---------------------------------------------------------------------------
#define S_PAD 26   // 25-bin pass + 1 pad (bank-conflict-friendly)

template <int NB, int BIN0>
__device__ __forceinline__ void gather_pass(const float4* __restrict__ ii4,
                                            const int* __restrict__ soff,
                                            const float* __restrict__ srarea,
                                            float* __restrict__ sh,
                                            float* __restrict__ outn,
                                            int tid) {
    const int cg = tid & 63;      // channel group (4 channels via float4)
    const int slot = tid >> 6;    // 0..3

    #pragma unroll
    for (int b = slot; b < NB; b += 4) {
        const int bb = BIN0 + b;
        const int o0 = soff[bb * 4 + 0];
        const int o1 = soff[bb * 4 + 1];
        const int o2 = soff[bb * 4 + 2];
        const int o3 = soff[bb * 4 + 3];
        const float4 A = ii4[o0 + cg];
        const float4 B = ii4[o1 + cg];
        const float4 C = ii4[o2 + cg];
        const float4 D = ii4[o3 + cg];
        const float ra = srarea[bb];
        const int cb = cg * 4;
        sh[(cb + 0) * S_PAD + b] = (A.x - B.x - C.x + D.x) * ra;
        sh[(cb + 1) * S_PAD + b] = (A.y - B.y - C.y + D.y) * ra;
        sh[(cb + 2) * S_PAD + b] = (A.z - B.z - C.z + D.z) * ra;
        sh[(cb + 3) * S_PAD + b] = (A.w - B.w - C.w + D.w) * ra;
    }
    __syncthreads();
    // coalesced flat write-out: idx -> (c = idx/NB, b = idx%NB), NB constexpr
    #pragma unroll 4
    for (int idx = tid; idx < FM_C * NB; idx += 256) {
        const int c = idx / NB;
        const int b = idx - c * NB;
        outn[c * NBINS + BIN0 + b] = sh[c * S_PAD + b];
    }
    __syncthreads();
}

__global__ void __launch_bounds__(256) k3_gather(const float* __restrict__ boxes,
                                                 float* __restrict__ out) {
    __shared__ float sh[FM_C * S_PAD];     // 26.6 KB
    __shared__ int   soff[NBINS * 4];
    __shared__ float srarea[NBINS];
    const int n = blockIdx.x;
    const int tid = threadIdx.x;

    if (tid < NBINS) {
        const float bx1 = __ldg(&boxes[n * 4 + 0]);
        const float by1 = __ldg(&boxes[n * 4 + 1]);
        const float bx2 = __ldg(&boxes[n * 4 + 2]);
        const float by2 = __ldg(&boxes[n * 4 + 3]);

        // scale = 200/800 = 0.25 exactly (bit-exact with reference)
        const int b0 = (int)floorf(bx1 * 0.25f);
        const int b1 = (int)floorf(by1 * 0.25f);
        const int b2 = (int)floorf(bx2 * 0.25f);
        const int b3 = (int)floorf(by2 * 0.25f);

        const int x1 = min(max(b0, 0), FM_W - 1);
        const int y1 = min(max(b1, 0), FM_H - 1);
        const int x2 = min(max(b2 + 1, x1 + 1), FM_W);
        const int y2 = min(max(b3 + 1, y1 + 1), FM_H);
        const int rh = y2 - y1;
        const int rw = x2 - x1;

        const int i = tid / OW;
        const int j = tid - i * OW;
        const int rs_ = y1 + (i * rh) / OH;
        const int re_ = y1 + ((i + 1) * rh + OH - 1) / OH;
        const int cs_ = x1 + (j * rw) / OW;
        const int ce_ = x1 + ((j + 1) * rw + OW - 1) / OW;

        // float4 offsets: (r*IIW + col) * (FM_C/4)
        soff[tid * 4 + 0] = (re_ * IIW + ce_) * (FM_C / 4);
        soff[tid * 4 + 1] = (rs_ * IIW + ce_) * (FM_C / 4);
        soff[tid * 4 + 2] = (re_ * IIW + cs_) * (FM_C / 4);
        soff[tid * 4 + 3] = (rs_ * IIW + cs_) * (FM_C / 4);
        srarea[tid] = 1.0f / (float)((re_ - rs_) * (ce_ - cs_));
    }
    __syncthreads();

    const float4* ii4 = (const float4*)g_ii;
    float* outn = out + (size_t)n * (FM_C * NBINS);

    gather_pass<25, 0>(ii4, soff, srarea, sh, outn, tid);
    gather_pass<24, 25>(ii4, soff, srarea, sh, outn, tid);
}

// ---------------------------------------------------------------------------
extern "C" void kernel_launch(void* const* d_in, const int* in_sizes, int n_in,
                              void* d_out, int out_size) {
    const float* fm    = (const float*)d_in[0];   // [1,256,200,200] fp32
    const float* boxes = (const float*)d_in[1];   // [1024,4] fp32
    float* out = (float*)d_out;                   // [1024,256,7,7] fp32

    {
        int nmax = IIW * FM_C;
        k0_zero_pad<<<(nmax + 255) / 256, 256>>>();
    }
    {
        dim3 grid((FM_W + TX - 1) / TX, FM_C / TC);  // (13, 8)
        k1_ycum_transpose<<<grid, 512>>>(fm);
    }
    k2_xcum<<<FM_H, 256>>>();
    k3_gather<<<NBOX, 256>>>(boxes, out);
}

// round 3
// speedup vs baseline: 2.2436x; 1.9427x over previous
#include <cuda_runtime.h>
#include <math.h>

#define FM_C 256
#define FM_H 200
#define FM_W 200
#define IIH 201
#define IIW 201
#define NBOX 1024
#define OH 7
#define OW 7
#define NBINS 49

// Integral image scratch, channel-last layout: [y][x][c], y,x in 0..200.
__device__ float g_ii[IIH * IIW * FM_C];  // 41.4 MB

// ---------------------------------------------------------------------------
// K0: zero the padding (y=0 plane and x=0 column)
// ---------------------------------------------------------------------------
__global__ void k0_zero_pad() {
    int idx = blockIdx.x * blockDim.x + threadIdx.x;
    if (idx < IIW * FM_C) {
        g_ii[idx] = 0.0f;
    }
    if (idx < (IIH - 1) * FM_C) {
        int y = idx / FM_C + 1;
        int c = idx % FM_C;
        g_ii[(y * IIW) * FM_C + c] = 0.0f;
    }
}

// ---------------------------------------------------------------------------
// K1: cumsum over y, fused with transpose [C][H][W] -> [y+1][x+1][C].
// Chunked: 4 y-rows per barrier; triple-buffered register prefetch gives a
// 12-row lead (~3 chunk periods) to cover the ~577-cycle DRAM latency.
// ---------------------------------------------------------------------------
#define TX 16
#define TC 32
#define YC 4
#define NCHUNK (FM_H / YC)   // 50

__global__ void __launch_bounds__(512) k1_ycum_transpose(const float* __restrict__ fm) {
    __shared__ float sh[2][YC][TC][TX + 1];
    const int tid = threadIdx.x;           // 0..511
    const int x0 = blockIdx.x * TX;
    const int c0 = blockIdx.y * TC;

    // Load-side mapping: contiguous x within a 16-thread group
    const int xx = tid & (TX - 1);
    const int cc = tid >> 4;
    const int xr = x0 + xx;
    const bool valid = (xr < FM_W);
    const float* src = fm + (size_t)(c0 + cc) * (FM_H * FM_W) + xr;

    // Store-side mapping: contiguous c within a warp (128B coalesced stores)
    const int c_out = tid & 31;
    const int x_out = tid >> 5;
    const bool validw = (x0 + x_out) < FM_W;
    float* dstbase = g_ii + (size_t)(x0 + x_out + 1) * FM_C + (c0 + c_out);

    float b0[YC], b1[YC], b2[YC];
    #pragma unroll
    for (int k = 0; k < YC; k++) {
        int r0 = 0 * YC + k, r1 = 1 * YC + k, r2 = 2 * YC + k;
        b0[k] = (valid && r0 < FM_H) ? src[r0 * FM_W] : 0.0f;
        b1[k] = (valid && r1 < FM_H) ? src[r1 * FM_W] : 0.0f;
        b2[k] = (valid && r2 < FM_H) ? src[r2 * FM_W] : 0.0f;
    }

    float acc = 0.0f;
    #pragma unroll 1
    for (int ch = 0; ch < NCHUNK; ch++) {
        const int buf = ch & 1;
        // consume b0 into shared
        #pragma unroll
        for (int k = 0; k < YC; k++) {
            acc += b0[k];
            sh[buf][k][cc][xx] = acc;
        }
        // rotate and prefetch chunk ch+3
        #pragma unroll
        for (int k = 0; k < YC; k++) { b0[k] = b1[k]; b1[k] = b2[k]; }
        {
            const int rb = (ch + 3) * YC;
            #pragma unroll
            for (int k = 0; k < YC; k++) {
                const int r = rb + k;
                b2[k] = (valid && r < FM_H) ? src[r * FM_W] : 0.0f;
            }
        }
        __syncthreads();
        if (validw) {
            const size_t rowbase = (size_t)(ch * YC + 1) * (IIW * FM_C);
            #pragma unroll
            for (int k = 0; k < YC; k++) {
                dstbase[rowbase + (size_t)k * (IIW * FM_C)] = sh[buf][k][c_out][x_out];
            }
        }
        // double buffer: next chunk writes the other buffer; writes to this
        // buffer again only after the next barrier, which follows all reads.
    }
}

// ---------------------------------------------------------------------------
// K2: cumsum over x, in-place, channel-last layout. Thread per (y, c-half).
// Explicit 20-wide load batch -> serial accumulate -> store batch: MLP=20.
// ---------------------------------------------------------------------------
#define K2B 20
__global__ void __launch_bounds__(128) k2_xcum() {
    const int y = blockIdx.x + 1;                       // 1..200
    const int c = blockIdx.y * 128 + threadIdx.x;       // 0..255
    float* row = g_ii + (size_t)(y * IIW) * FM_C + c;
    float acc = 0.0f;
    #pragma unroll 1
    for (int xb = 1; xb <= FM_W; xb += K2B) {
        float v[K2B];
        #pragma unroll
        for (int j = 0; j < K2B; j++) v[j] = row[(size_t)(xb + j) * FM_C];
        #pragma unroll
        for (int j = 0; j < K2B; j++) { acc += v[j]; v[j] = acc; }
        #pragma unroll
        for (int j = 0; j < K2B; j++) row[(size_t)(xb + j) * FM_C] = v[j];
    }
}

// ---------------------------------------------------------------------------
// K3: gather. One block per box.
//  warp lanes = 8 channel-groups x 4 bins: loads stay 4x128B wavefronts,
//  staging stores drop from 8-way to 2-way bank conflicts.
// ---------------------------------------------------------------------------
#define S_PAD 26

template <int NB, int BIN0>
__device__ __forceinline__ void gather_pass(const float4* __restrict__ ii4,
                                            const int* __restrict__ soff,
                                            const float* __restrict__ srarea,
                                            float* __restrict__ sh,
                                            float* __restrict__ outn,
                                            int tid) {
    const int warp = tid >> 5;
    const int lane = tid & 31;
    const int cg = warp * 8 + (lane & 7);   // 0..63 channel group (float4)
    const int bsl = lane >> 3;              // 0..3 bin slot

    #pragma unroll
    for (int bb = bsl; bb < NB; bb += 4) {
        const int b = BIN0 + bb;
        const int o0 = soff[b * 4 + 0];
        const int o1 = soff[b * 4 + 1];
        const int o2 = soff[b * 4 + 2];
        const int o3 = soff[b * 4 + 3];
        const float4 A = ii4[o0 + cg];
        const float4 B = ii4[o1 + cg];
        const float4 C = ii4[o2 + cg];
        const float4 D = ii4[o3 + cg];
        const float ra = srarea[b];
        const int cb = cg * 4;
        sh[(cb + 0) * S_PAD + bb] = (A.x - B.x - C.x + D.x) * ra;
        sh[(cb + 1) * S_PAD + bb] = (A.y - B.y - C.y + D.y) * ra;
        sh[(cb + 2) * S_PAD + bb] = (A.z - B.z - C.z + D.z) * ra;
        sh[(cb + 3) * S_PAD + bb] = (A.w - B.w - C.w + D.w) * ra;
    }
    __syncthreads();
    #pragma unroll 4
    for (int idx = tid; idx < FM_C * NB; idx += 256) {
        const int c = idx / NB;               // NB constexpr -> magic multiply
        const int b = idx - c * NB;
        outn[c * NBINS + BIN0 + b] = sh[c * S_PAD + b];
    }
    __syncthreads();
}

__global__ void __launch_bounds__(256) k3_gather(const float* __restrict__ boxes,
                                                 float* __restrict__ out) {
    __shared__ float sh[FM_C * S_PAD];     // 26.6 KB
    __shared__ int   soff[NBINS * 4];
    __shared__ float srarea[NBINS];
    const int n = blockIdx.x;
    const int tid = threadIdx.x;

    if (tid < NBINS) {
        const float bx1 = __ldg(&boxes[n * 4 + 0]);
        const float by1 = __ldg(&boxes[n * 4 + 1]);
        const float bx2 = __ldg(&boxes[n * 4 + 2]);
        const float by2 = __ldg(&boxes[n * 4 + 3]);

        // scale = 200/800 = 0.25 exactly (bit-exact with reference)
        const int b0 = (int)floorf(bx1 * 0.25f);
        const int b1 = (int)floorf(by1 * 0.25f);
        const int b2 = (int)floorf(bx2 * 0.25f);
        const int b3 = (int)floorf(by2 * 0.25f);

        const int x1 = min(max(b0, 0), FM_W - 1);
        const int y1 = min(max(b1, 0), FM_H - 1);
        const int x2 = min(max(b2 + 1, x1 + 1), FM_W);
        const int y2 = min(max(b3 + 1, y1 + 1), FM_H);
        const int rh = y2 - y1;
        const int rw = x2 - x1;

        const int i = tid / OW;
        const int j = tid - i * OW;
        const int rs_ = y1 + (i * rh) / OH;
        const int re_ = y1 + ((i + 1) * rh + OH - 1) / OH;
        const int cs_ = x1 + (j * rw) / OW;
        const int ce_ = x1 + ((j + 1) * rw + OW - 1) / OW;

        soff[tid * 4 + 0] = (re_ * IIW + ce_) * (FM_C / 4);
        soff[tid * 4 + 1] = (rs_ * IIW + ce_) * (FM_C / 4);
        soff[tid * 4 + 2] = (re_ * IIW + cs_) * (FM_C / 4);
        soff[tid * 4 + 3] = (rs_ * IIW + cs_) * (FM_C / 4);
        srarea[tid] = 1.0f / (float)((re_ - rs_) * (ce_ - cs_));
    }
    __syncthreads();

    const float4* ii4 = (const float4*)g_ii;
    float* outn = out + (size_t)n * (FM_C * NBINS);

    gather_pass<25, 0>(ii4, soff, srarea, sh, outn, tid);
    gather_pass<24, 25>(ii4, soff, srarea, sh, outn, tid);
}

// ---------------------------------------------------------------------------
extern "C" void kernel_launch(void* const* d_in, const int* in_sizes, int n_in,
                              void* d_out, int out_size) {
    const float* fm    = (const float*)d_in[0];   // [1,256,200,200] fp32
    const float* boxes = (const float*)d_in[1];   // [1024,4] fp32
    float* out = (float*)d_out;                   // [1024,256,7,7] fp32

    {
        int nmax = IIW * FM_C;
        k0_zero_pad<<<(nmax + 255) / 256, 256>>>();
    }
    {
        dim3 grid((FM_W + TX - 1) / TX, FM_C / TC);  // (13, 8)
        k1_ycum_transpose<<<grid, 512>>>(fm);
    }
    {
        dim3 grid(FM_H, 2);                          // (200, 2)
        k2_xcum<<<grid, 128>>>();
    }
    k3_gather<<<NBOX, 256>>>(boxes, out);
}

// round 4
// speedup vs baseline: 2.5296x; 1.1275x over previous
#include <cuda_runtime.h>
#include <math.h>

#define FM_C 256
#define FM_H 200
#define FM_W 200
#define IIH 201
#define IIW 201
#define NBOX 1024
#define OH 7
#define OW 7
#define NBINS 49

// Integral image scratch, channel-last layout: [y][x][c], y,x in 0..200.
__device__ float g_ii[IIH * IIW * FM_C];  // 41.4 MB

// ---------------------------------------------------------------------------
// K0: zero the padding (y=0 plane and x=0 column)
// ---------------------------------------------------------------------------
__global__ void k0_zero_pad() {
    int idx = blockIdx.x * blockDim.x + threadIdx.x;
    if (idx < IIW * FM_C) {
        g_ii[idx] = 0.0f;
    }
    if (idx < (IIH - 1) * FM_C) {
        int y = idx / FM_C + 1;
        int c = idx % FM_C;
        g_ii[(y * IIW) * FM_C + c] = 0.0f;
    }
}

// ---------------------------------------------------------------------------
// K1: cumsum over y, fused with transpose [C][H][W] -> [y+1][x+1][C].
// 208 blocks (16 c-tiles x 13 x-tiles) of 256 threads: every SM occupied.
// YC=8 rows per barrier (25 barriers total); depth-2 chunk prefetch gives a
// 16-row lead to cover DRAM latency.
// ---------------------------------------------------------------------------
#define TX 16
#define TC 16
#define YC 8
#define NCHUNK (FM_H / YC)   // 25

__global__ void __launch_bounds__(256) k1_ycum_transpose(const float* __restrict__ fm) {
    __shared__ float sh[2][YC][TC][TX + 1];
    const int tid = threadIdx.x;           // 0..255
    const int x0 = blockIdx.x * TX;
    const int c0 = blockIdx.y * TC;

    // Load-side mapping: contiguous x within a 16-thread group
    const int xx = tid & (TX - 1);         // 0..15
    const int cc = tid >> 4;               // 0..15
    const int xr = x0 + xx;
    const bool valid = (xr < FM_W);
    const float* src = fm + (size_t)(c0 + cc) * (FM_H * FM_W) + xr;

    // Store-side mapping: contiguous c within a 16-thread group
    const int c_out = tid & 15;
    const int x_out = tid >> 4;
    const bool validw = (x0 + x_out) < FM_W;
    float* dstbase = g_ii + (size_t)(x0 + x_out + 1) * FM_C + (c0 + c_out);

    float b0[YC], b1[YC];
    #pragma unroll
    for (int k = 0; k < YC; k++) {
        b0[k] = valid ? src[(0 * YC + k) * FM_W] : 0.0f;
        b1[k] = valid ? src[(1 * YC + k) * FM_W] : 0.0f;
    }

    float acc = 0.0f;
    #pragma unroll 1
    for (int ch = 0; ch < NCHUNK; ch++) {
        const int buf = ch & 1;
        #pragma unroll
        for (int k = 0; k < YC; k++) {
            acc += b0[k];
            sh[buf][k][cc][xx] = acc;
        }
        // rotate; prefetch chunk ch+2
        #pragma unroll
        for (int k = 0; k < YC; k++) b0[k] = b1[k];
        {
            const int rb = (ch + 2) * YC;
            #pragma unroll
            for (int k = 0; k < YC; k++) {
                const int r = rb + k;
                b1[k] = (valid && r < FM_H) ? src[r * FM_W] : 0.0f;
            }
        }
        __syncthreads();
        if (validw) {
            const size_t rowbase = (size_t)(ch * YC + 1) * (IIW * FM_C);
            #pragma unroll
            for (int k = 0; k < YC; k++) {
                dstbase[rowbase + (size_t)k * (IIW * FM_C)] = sh[buf][k][c_out][x_out];
            }
        }
        // double buffer: next chunk writes the other buffer; this buffer is
        // rewritten only after the next barrier, which follows all its reads.
    }
}

// ---------------------------------------------------------------------------
// K2: cumsum over x, in-place, channel-last layout. One block per y-row,
// thread per channel. Double-buffered batches: load batch i+1 while
// accumulating batch i -> L2 latency paid once, not per batch.
// ---------------------------------------------------------------------------
#define K2B 20
#define K2NB (FM_W / K2B)    // 10
__global__ void __launch_bounds__(256) k2_xcum() {
    const int y = blockIdx.x + 1;          // 1..200
    const int c = threadIdx.x;             // 0..255
    float* row = g_ii + (size_t)(y * IIW) * FM_C + c;

    float va[K2B], vb[K2B];
    #pragma unroll
    for (int j = 0; j < K2B; j++) va[j] = row[(size_t)(1 + j) * FM_C];

    float acc = 0.0f;
    #pragma unroll 1
    for (int i = 0; i < K2NB; i++) {
        // prefetch next batch into the alternate buffer
        if (i + 1 < K2NB) {
            const int xb = 1 + (i + 1) * K2B;
            #pragma unroll
            for (int j = 0; j < K2B; j++) vb[j] = row[(size_t)(xb + j) * FM_C];
        }
        const int x0_ = 1 + i * K2B;
        #pragma unroll
        for (int j = 0; j < K2B; j++) {
            acc += va[j];
            row[(size_t)(x0_ + j) * FM_C] = acc;
        }
        #pragma unroll
        for (int j = 0; j < K2B; j++) va[j] = vb[j];
    }
}

// ---------------------------------------------------------------------------
// K3: gather. One block per box.
//  warp lanes = 8 channel-groups x 4 bins; S_PAD=25 makes staging stores
//  conflict-free (lane stride 100 = 4 mod 32, x4 groups + bin offset -> all
//  32 banks) and the 25-bin readback exactly linear.
// ---------------------------------------------------------------------------
#define S_PAD 25

template <int NB, int BIN0>
__device__ __forceinline__ void gather_pass(const float4* __restrict__ ii4,
                                            const int* __restrict__ soff,
                                            const float* __restrict__ srarea,
                                            float* __restrict__ sh,
                                            float* __restrict__ outn,
                                            int tid) {
    const int warp = tid >> 5;
    const int lane = tid & 31;
    const int cg = warp * 8 + (lane & 7);   // 0..63 channel group (float4)
    const int bsl = lane >> 3;              // 0..3 bin slot

    #pragma unroll
    for (int bb = bsl; bb < NB; bb += 4) {
        const int b = BIN0 + bb;
        const int o0 = soff[b * 4 + 0];
        const int o1 = soff[b * 4 + 1];
        const int o2 = soff[b * 4 + 2];
        const int o3 = soff[b * 4 + 3];
        const float4 A = ii4[o0 + cg];
        const float4 B = ii4[o1 + cg];
        const float4 C = ii4[o2 + cg];
        const float4 D = ii4[o3 + cg];
        const float ra = srarea[b];
        const int cb = cg * 4;
        sh[(cb + 0) * S_PAD + bb] = (A.x - B.x - C.x + D.x) * ra;
        sh[(cb + 1) * S_PAD + bb] = (A.y - B.y - C.y + D.y) * ra;
        sh[(cb + 2) * S_PAD + bb] = (A.z - B.z - C.z + D.z) * ra;
        sh[(cb + 3) * S_PAD + bb] = (A.w - B.w - C.w + D.w) * ra;
    }
    __syncthreads();
    #pragma unroll 4
    for (int idx = tid; idx < FM_C * NB; idx += 256) {
        const int c = idx / NB;               // NB constexpr -> magic multiply
        const int b = idx - c * NB;
        outn[c * NBINS + BIN0 + b] = sh[c * S_PAD + b];
    }
    __syncthreads();
}

__global__ void __launch_bounds__(256) k3_gather(const float* __restrict__ boxes,
                                                 float* __restrict__ out) {
    __shared__ float sh[FM_C * S_PAD];     // 25.6 KB
    __shared__ int   soff[NBINS * 4];
    __shared__ float srarea[NBINS];
    const int n = blockIdx.x;
    const int tid = threadIdx.x;

    if (tid < NBINS) {
        const float bx1 = __ldg(&boxes[n * 4 + 0]);
        const float by1 = __ldg(&boxes[n * 4 + 1]);
        const float bx2 = __ldg(&boxes[n * 4 + 2]);
        const float by2 = __ldg(&boxes[n * 4 + 3]);

        // scale = 200/800 = 0.25 exactly (bit-exact with reference)
        const int b0 = (int)floorf(bx1 * 0.25f);
        const int b1 = (int)floorf(by1 * 0.25f);
        const int b2 = (int)floorf(bx2 * 0.25f);
        const int b3 = (int)floorf(by2 * 0.25f);

        const int x1 = min(max(b0, 0), FM_W - 1);
        const int y1 = min(max(b1, 0), FM_H - 1);
        const int x2 = min(max(b2 + 1, x1 + 1), FM_W);
        const int y2 = min(max(b3 + 1, y1 + 1), FM_H);
        const int rh = y2 - y1;
        const int rw = x2 - x1;

        const int i = tid / OW;
        const int j = tid - i * OW;
        const int rs_ = y1 + (i * rh) / OH;
        const int re_ = y1 + ((i + 1) * rh + OH - 1) / OH;
        const int cs_ = x1 + (j * rw) / OW;
        const int ce_ = x1 + ((j + 1) * rw + OW - 1) / OW;

        soff[tid * 4 + 0] = (re_ * IIW + ce_) * (FM_C / 4);
        soff[tid * 4 + 1] = (rs_ * IIW + ce_) * (FM_C / 4);
        soff[tid * 4 + 2] = (re_ * IIW + cs_) * (FM_C / 4);
        soff[tid * 4 + 3] = (rs_ * IIW + cs_) * (FM_C / 4);
        srarea[tid] = 1.0f / (float)((re_ - rs_) * (ce_ - cs_));
    }
    __syncthreads();

    const float4* ii4 = (const float4*)g_ii;
    float* outn = out + (size_t)n * (FM_C * NBINS);

    gather_pass<25, 0>(ii4, soff, srarea, sh, outn, tid);
    gather_pass<24, 25>(ii4, soff, srarea, sh, outn, tid);
}

// ---------------------------------------------------------------------------
extern "C" void kernel_launch(void* const* d_in, const int* in_sizes, int n_in,
                              void* d_out, int out_size) {
    const float* fm    = (const float*)d_in[0];   // [1,256,200,200] fp32
    const float* boxes = (const float*)d_in[1];   // [1024,4] fp32
    float* out = (float*)d_out;                   // [1024,256,7,7] fp32

    {
        int nmax = IIW * FM_C;
        k0_zero_pad<<<(nmax + 255) / 256, 256>>>();
    }
    {
        dim3 grid((FM_W + TX - 1) / TX, FM_C / TC);  // (13, 16) = 208 blocks
        k1_ycum_transpose<<<grid, 256>>>(fm);
    }
    k2_xcum<<<FM_H, 256>>>();
    k3_gather<<<NBOX, 256>>>(boxes, out);
}

// round 5
// speedup vs baseline: 2.8194x; 1.1146x over previous
#include <cuda_runtime.h>
#include <math.h>

#define FM_C 256
#define FM_H 200
#define FM_W 200
#define IIH 201
#define IIW 201
#define NBOX 1024
#define OH 7
#define OW 7
#define NBINS 49

// Integral image scratch, channel-last layout: [y][x][c], y,x in 0..200.
__device__ float g_ii[IIH * IIW * FM_C];  // 41.4 MB

// ---------------------------------------------------------------------------
// K1: cumsum over y, fused with transpose [C][H][W] -> [y+1][x+1][C].
// Also writes the zero pads (y=0 plane; x=0 column) so no separate k0.
// 208 blocks (16 c-tiles x 13 x-tiles) of 256 threads.
// YC=8 rows per barrier (25 barriers); depth-2 chunk prefetch (16-row lead).
// ---------------------------------------------------------------------------
#define TX 16
#define TC 16
#define YC 8
#define NCHUNK (FM_H / YC)   // 25

__global__ void __launch_bounds__(256) k1_ycum_transpose(const float* __restrict__ fm) {
    __shared__ float sh[2][YC][TC][TX + 1];
    const int tid = threadIdx.x;           // 0..255
    const int x0 = blockIdx.x * TX;
    const int c0 = blockIdx.y * TC;

    // Load-side mapping: contiguous x within a 16-thread group
    const int xx = tid & (TX - 1);         // 0..15
    const int cc = tid >> 4;               // 0..15
    const int xr = x0 + xx;
    const bool valid = (xr < FM_W);
    const float* src = fm + (size_t)(c0 + cc) * (FM_H * FM_W) + xr;

    // Store-side mapping: contiguous c within a 16-thread group
    const int c_out = tid & 15;
    const int x_out = tid >> 4;
    const bool validw = (x0 + x_out) < FM_W;
    float* dstbase = g_ii + (size_t)(x0 + x_out + 1) * FM_C + (c0 + c_out);

    // --- zero pads ---
    // y = 0 plane for this block's (x,c) tile (one elem/thread):
    if (validw) {
        g_ii[(size_t)(x0 + x_out + 1) * FM_C + (c0 + c_out)] = 0.0f;  // [0][x+1][c]
    }
    if (blockIdx.x == 0) {
        // x = 0 column, y = 0..200 for this block's c-range: 201*16 elems / 256 thr
        for (int idx = tid; idx < IIH * TC; idx += 256) {
            const int y = idx / TC;
            const int c = idx - y * TC;
            g_ii[((size_t)y * IIW) * FM_C + (c0 + c)] = 0.0f;
        }
    }

    float b0[YC], b1[YC];
    #pragma unroll
    for (int k = 0; k < YC; k++) {
        b0[k] = valid ? __ldcs(&src[(0 * YC + k) * FM_W]) : 0.0f;
        b1[k] = valid ? __ldcs(&src[(1 * YC + k) * FM_W]) : 0.0f;
    }

    float acc = 0.0f;
    #pragma unroll 1
    for (int ch = 0; ch < NCHUNK; ch++) {
        const int buf = ch & 1;
        #pragma unroll
        for (int k = 0; k < YC; k++) {
            acc += b0[k];
            sh[buf][k][cc][xx] = acc;
        }
        // rotate; prefetch chunk ch+2 (evict-first: fm is never reused)
        #pragma unroll
        for (int k = 0; k < YC; k++) b0[k] = b1[k];
        {
            const int rb = (ch + 2) * YC;
            #pragma unroll
            for (int k = 0; k < YC; k++) {
                const int r = rb + k;
                b1[k] = (valid && r < FM_H) ? __ldcs(&src[r * FM_W]) : 0.0f;
            }
        }
        __syncthreads();
        if (validw) {
            const size_t rowbase = (size_t)(ch * YC + 1) * (IIW * FM_C);
            #pragma unroll
            for (int k = 0; k < YC; k++) {
                dstbase[rowbase + (size_t)k * (IIW * FM_C)] = sh[buf][k][c_out][x_out];
            }
        }
        // double buffer: this buffer is rewritten only after the next barrier,
        // which follows all its reads.
    }
}

// ---------------------------------------------------------------------------
// K2: cumsum over x, in-place, channel-last layout. One block per y-row,
// thread per channel. Double-buffered batches: load batch i+1 while
// accumulating batch i.
// ---------------------------------------------------------------------------
#define K2B 20
#define K2NB (FM_W / K2B)    // 10
__global__ void __launch_bounds__(256) k2_xcum() {
    const int y = blockIdx.x + 1;          // 1..200
    const int c = threadIdx.x;             // 0..255
    float* row = g_ii + (size_t)(y * IIW) * FM_C + c;

    float va[K2B], vb[K2B];
    #pragma unroll
    for (int j = 0; j < K2B; j++) va[j] = row[(size_t)(1 + j) * FM_C];

    float acc = 0.0f;
    #pragma unroll 1
    for (int i = 0; i < K2NB; i++) {
        if (i + 1 < K2NB) {
            const int xb = 1 + (i + 1) * K2B;
            #pragma unroll
            for (int j = 0; j < K2B; j++) vb[j] = row[(size_t)(xb + j) * FM_C];
        }
        const int x0_ = 1 + i * K2B;
        #pragma unroll
        for (int j = 0; j < K2B; j++) {
            acc += va[j];
            row[(size_t)(x0_ + j) * FM_C] = acc;
        }
        #pragma unroll
        for (int j = 0; j < K2B; j++) va[j] = vb[j];
    }
}

// ---------------------------------------------------------------------------
// K3: gather. One block per TWO boxes (512 blocks -> single wave).
// warp lanes = 8 channel-groups x 4 bins; S_PAD=25 conflict-free staging.
// Output stores use evict-first (.cs) so streaming writes don't evict the
// L2-resident integral image.
// ---------------------------------------------------------------------------
#define S_PAD 25
#define BPB 2   // boxes per block

template <int NB, int BIN0>
__device__ __forceinline__ void gather_pass(const float4* __restrict__ ii4,
                                            const int* __restrict__ soff,
                                            const float* __restrict__ srarea,
                                            float* __restrict__ sh,
                                            float* __restrict__ outn,
                                            int tid) {
    const int warp = tid >> 5;
    const int lane = tid & 31;
    const int cg = warp * 8 + (lane & 7);   // 0..63 channel group (float4)
    const int bsl = lane >> 3;              // 0..3 bin slot

    #pragma unroll
    for (int bb = bsl; bb < NB; bb += 4) {
        const int b = BIN0 + bb;
        const int o0 = soff[b * 4 + 0];
        const int o1 = soff[b * 4 + 1];
        const int o2 = soff[b * 4 + 2];
        const int o3 = soff[b * 4 + 3];
        const float4 A = ii4[o0 + cg];
        const float4 B = ii4[o1 + cg];
        const float4 C = ii4[o2 + cg];
        const float4 D = ii4[o3 + cg];
        const float ra = srarea[b];
        const int cb = cg * 4;
        sh[(cb + 0) * S_PAD + bb] = (A.x - B.x - C.x + D.x) * ra;
        sh[(cb + 1) * S_PAD + bb] = (A.y - B.y - C.y + D.y) * ra;
        sh[(cb + 2) * S_PAD + bb] = (A.z - B.z - C.z + D.z) * ra;
        sh[(cb + 3) * S_PAD + bb] = (A.w - B.w - C.w + D.w) * ra;
    }
    __syncthreads();
    #pragma unroll 4
    for (int idx = tid; idx < FM_C * NB; idx += 256) {
        const int c = idx / NB;               // NB constexpr -> magic multiply
        const int b = idx - c * NB;
        __stcs(&outn[c * NBINS + BIN0 + b], sh[c * S_PAD + b]);
    }
    __syncthreads();
}

__global__ void __launch_bounds__(256) k3_gather(const float* __restrict__ boxes,
                                                 float* __restrict__ out) {
    __shared__ float sh[FM_C * S_PAD];       // 25.6 KB
    __shared__ int   soff[BPB][NBINS * 4];
    __shared__ float srarea[BPB][NBINS];
    const int tid = threadIdx.x;

    // Setup both boxes' bin tables upfront: threads 0..97, tid/49 selects box.
    if (tid < BPB * NBINS) {
        const int bx = tid / NBINS;
        const int bin = tid - bx * NBINS;
        const int n = blockIdx.x * BPB + bx;

        const float bx1 = __ldg(&boxes[n * 4 + 0]);
        const float by1 = __ldg(&boxes[n * 4 + 1]);
        const float bx2 = __ldg(&boxes[n * 4 + 2]);
        const float by2 = __ldg(&boxes[n * 4 + 3]);

        // scale = 200/800 = 0.25 exactly (bit-exact with reference)
        const int b0 = (int)floorf(bx1 * 0.25f);
        const int b1 = (int)floorf(by1 * 0.25f);
        const int b2 = (int)floorf(bx2 * 0.25f);
        const int b3 = (int)floorf(by2 * 0.25f);

        const int x1 = min(max(b0, 0), FM_W - 1);
        const int y1 = min(max(b1, 0), FM_H - 1);
        const int x2 = min(max(b2 + 1, x1 + 1), FM_W);
        const int y2 = min(max(b3 + 1, y1 + 1), FM_H);
        const int rh = y2 - y1;
        const int rw = x2 - x1;

        const int i = bin / OW;
        const int j = bin - i * OW;
        const int rs_ = y1 + (i * rh) / OH;
        const int re_ = y1 + ((i + 1) * rh + OH - 1) / OH;
        const int cs_ = x1 + (j * rw) / OW;
        const int ce_ = x1 + ((j + 1) * rw + OW - 1) / OW;

        soff[bx][bin * 4 + 0] = (re_ * IIW + ce_) * (FM_C / 4);
        soff[bx][bin * 4 + 1] = (rs_ * IIW + ce_) * (FM_C / 4);
        soff[bx][bin * 4 + 2] = (re_ * IIW + cs_) * (FM_C / 4);
        soff[bx][bin * 4 + 3] = (rs_ * IIW + cs_) * (FM_C / 4);
        srarea[bx][bin] = 1.0f / (float)((re_ - rs_) * (ce_ - cs_));
    }
    __syncthreads();

    const float4* ii4 = (const float4*)g_ii;

    #pragma unroll
    for (int bx = 0; bx < BPB; bx++) {
        const int n = blockIdx.x * BPB + bx;
        float* outn = out + (size_t)n * (FM_C * NBINS);
        gather_pass<25, 0>(ii4, soff[bx], srarea[bx], sh, outn, tid);
        gather_pass<24, 25>(ii4, soff[bx], srarea[bx], sh, outn, tid);
    }
}

// ---------------------------------------------------------------------------
extern "C" void kernel_launch(void* const* d_in, const int* in_sizes, int n_in,
                              void* d_out, int out_size) {
    const float* fm    = (const float*)d_in[0];   // [1,256,200,200] fp32
    const float* boxes = (const float*)d_in[1];   // [1024,4] fp32
    float* out = (float*)d_out;                   // [1024,256,7,7] fp32

    {
        dim3 grid((FM_W + TX - 1) / TX, FM_C / TC);  // (13, 16) = 208 blocks
        k1_ycum_transpose<<<grid, 256>>>(fm);
    }
    k2_xcum<<<FM_H, 256>>>();
    k3_gather<<<NBOX / BPB, 256>>>(boxes, out);
}